// round 4
// baseline (speedup 1.0000x reference)
#include <cuda_runtime.h>
#include <cuda_bf16.h>

// Problem constants (fixed shapes per reference)
#define N_NODES   100000
#define N_EDGES   1600000
#define IN_FEATS  128
#define OUT_FEATS 64

// Scratch: projected features h = feat @ W^T + b  (25.6 MB)
__device__ float g_h[(size_t)N_NODES * OUT_FEATS];
// Scratch: int32 edge indices (dtype-normalized)
__device__ int g_src32[N_EDGES];
__device__ int g_dst32[N_EDGES];
// Dtype detection flag: nonzero => index buffers are int32
__device__ unsigned int g_is_i32;

// ---------------------------------------------------------------------------
// Vector reduction helper: red.global.add.v4.f32 on sm_90+, scalar fallback.
// ---------------------------------------------------------------------------
__device__ __forceinline__ void red_add_v4(float* p, float4 m) {
#if defined(__CUDA_ARCH__) && (__CUDA_ARCH__ >= 900)
    asm volatile("red.global.add.v4.f32 [%0], {%1, %2, %3, %4};"
                 :: "l"(p), "f"(m.x), "f"(m.y), "f"(m.z), "f"(m.w)
                 : "memory");
#else
    atomicAdd(p + 0, m.x);
    atomicAdd(p + 1, m.y);
    atomicAdd(p + 2, m.z);
    atomicAdd(p + 3, m.w);
#endif
}

// ---------------------------------------------------------------------------
// Kernel 1: zero output accumulator + clear detection flag
// ---------------------------------------------------------------------------
__global__ __launch_bounds__(256) void zero_kernel(float4* out, int n4) {
    int i = blockIdx.x * blockDim.x + threadIdx.x;
    if (i == 0) g_is_i32 = 0u;
    if (i < n4) out[i] = make_float4(0.f, 0.f, 0.f, 0.f);
}

// ---------------------------------------------------------------------------
// Kernel 1b: dtype detection. Inspect the first 4*N_EDGES bytes of the src
// buffer (safe under either dtype) as uints. Odd-index words are int64 high
// words (all zero, since indices < 100000) OR real int32 indices (almost
// surely some nonzero). Any nonzero odd word => int32 layout.
// ---------------------------------------------------------------------------
__global__ __launch_bounds__(256) void detect_kernel(const unsigned int* __restrict__ buf) {
    // odd words: indices 1, 3, ..., covering N_EDGES words total (N_EDGES/2 odd ones)
    unsigned int lor = 0;
    int nhalf = N_EDGES / 2;
    for (int i = blockIdx.x * blockDim.x + threadIdx.x;
         i < nhalf;
         i += gridDim.x * blockDim.x) {
        lor |= buf[2 * i + 1];
    }
    unsigned int any = __ballot_sync(0xffffffffu, lor != 0u);
    if ((threadIdx.x & 31) == 0 && any) g_is_i32 = 1u;  // same-value store, race-free
}

// ---------------------------------------------------------------------------
// Kernel 1c: normalize indices to int32 with bounds clamp.
// ---------------------------------------------------------------------------
__global__ __launch_bounds__(256) void convert_kernel(const void* __restrict__ srcb,
                                                      const void* __restrict__ dstb) {
    int i = blockIdx.x * blockDim.x + threadIdx.x;
    if (i >= N_EDGES) return;
    unsigned int i32 = g_is_i32;
    int s, d;
    if (i32) {
        s = ((const int*)srcb)[i];
        d = ((const int*)dstb)[i];
    } else {
        s = (int)((const long long*)srcb)[i];
        d = (int)((const long long*)dstb)[i];
    }
    g_src32[i] = ((unsigned)s < (unsigned)N_NODES) ? s : 0;
    g_dst32[i] = ((unsigned)d < (unsigned)N_NODES) ? d : 0;
}

// ---------------------------------------------------------------------------
// Kernel 2: tiled fp32 GEMM  h[n][o] = sum_k feat[n][k] * W[o][k] + b[o]
// Block: 256 threads, tile = 128 nodes x 64 outs, K in chunks of 32.
// Each thread: 8 nodes x 4 outs = 32 accumulators.
// ---------------------------------------------------------------------------
#define MT 128
#define KT 32

__global__ __launch_bounds__(256) void gemm_kernel(
    const float* __restrict__ feat,
    const float* __restrict__ W,
    const float* __restrict__ b)
{
    __shared__ float sf[KT][MT];        // feat tile, transposed: [k][node]  (16KB)
    __shared__ float sw[KT][OUT_FEATS]; // W tile, transposed:    [k][out]   (8KB)

    const int tid    = threadIdx.x;
    const int block0 = blockIdx.x * MT;
    const int oc     = (tid & 15) * 4;  // 4 consecutive outputs
    const int nr     = (tid >> 4) * 8;  // 8 consecutive nodes

    float acc[8][4];
#pragma unroll
    for (int i = 0; i < 8; i++)
#pragma unroll
        for (int j = 0; j < 4; j++) acc[i][j] = 0.f;

    for (int kb = 0; kb < IN_FEATS; kb += KT) {
#pragma unroll
        for (int t = 0; t < 4; t++) {
            int l    = tid + t * 256;   // 0..1023
            int node = l >> 3;          // 0..127
            int kq   = l & 7;
            float4 v = make_float4(0.f, 0.f, 0.f, 0.f);
            int gn = block0 + node;
            if (gn < N_NODES)
                v = *(const float4*)(feat + (size_t)gn * IN_FEATS + kb + kq * 4);
            sf[kq * 4 + 0][node] = v.x;
            sf[kq * 4 + 1][node] = v.y;
            sf[kq * 4 + 2][node] = v.z;
            sf[kq * 4 + 3][node] = v.w;
        }
#pragma unroll
        for (int t = 0; t < 2; t++) {
            int l  = tid + t * 256;     // 0..511
            int o  = l >> 3;            // 0..63
            int kq = l & 7;
            float4 v = *(const float4*)(W + (size_t)o * IN_FEATS + kb + kq * 4);
            sw[kq * 4 + 0][o] = v.x;
            sw[kq * 4 + 1][o] = v.y;
            sw[kq * 4 + 2][o] = v.z;
            sw[kq * 4 + 3][o] = v.w;
        }
        __syncthreads();

#pragma unroll
        for (int kk = 0; kk < KT; kk++) {
            float a[8], w[4];
            *(float4*)&a[0] = *(const float4*)&sf[kk][nr];
            *(float4*)&a[4] = *(const float4*)&sf[kk][nr + 4];
            *(float4*)&w[0] = *(const float4*)&sw[kk][oc];
#pragma unroll
            for (int i = 0; i < 8; i++)
#pragma unroll
                for (int j = 0; j < 4; j++)
                    acc[i][j] += a[i] * w[j];
        }
        __syncthreads();
    }

    float4 bias = *(const float4*)(b + oc);
#pragma unroll
    for (int i = 0; i < 8; i++) {
        int gn = block0 + nr + i;
        if (gn < N_NODES) {
            float4 r;
            r.x = acc[i][0] + bias.x;
            r.y = acc[i][1] + bias.y;
            r.z = acc[i][2] + bias.z;
            r.w = acc[i][3] + bias.w;
            *(float4*)(g_h + (size_t)gn * OUT_FEATS + oc) = r;
        }
    }
}

// ---------------------------------------------------------------------------
// Kernel 3: edge scatter. 16 threads per edge, each owns one float4 of the
// 64-wide row. Gather h[src] (coalesced 256B/edge), scale by e, vector-RED
// into out[dst].
// ---------------------------------------------------------------------------
__global__ __launch_bounds__(256) void edge_kernel(
    const float* __restrict__ e,
    float*       __restrict__ out)
{
    long long idx = (long long)blockIdx.x * blockDim.x + threadIdx.x;
    int eid  = (int)(idx >> 4);
    int lane = (int)(idx & 15);
    if (eid >= N_EDGES) return;

    int   s = g_src32[eid];
    int   d = g_dst32[eid];
    float w = e[eid];

    float4 h4 = *(const float4*)(g_h + (size_t)s * OUT_FEATS + lane * 4);
    float4 m;
    m.x = h4.x * w;
    m.y = h4.y * w;
    m.z = h4.z * w;
    m.w = h4.w * w;

    red_add_v4(out + (size_t)d * OUT_FEATS + lane * 4, m);
}

// ---------------------------------------------------------------------------
// Kernel 4: in-place relu
// ---------------------------------------------------------------------------
__global__ __launch_bounds__(256) void relu_kernel(float4* out, int n4) {
    int i = blockIdx.x * blockDim.x + threadIdx.x;
    if (i < n4) {
        float4 v = out[i];
        v.x = fmaxf(v.x, 0.f);
        v.y = fmaxf(v.y, 0.f);
        v.z = fmaxf(v.z, 0.f);
        v.w = fmaxf(v.w, 0.f);
        out[i] = v;
    }
}

// ---------------------------------------------------------------------------
extern "C" void kernel_launch(void* const* d_in, const int* in_sizes, int n_in,
                              void* d_out, int out_size)
{
    const float* feat = (const float*)d_in[0];
    const void*  src  = d_in[1];
    const void*  dst  = d_in[2];
    const float* e    = (const float*)d_in[3];
    const float* W_w  = (const float*)d_in[4];
    const float* W_b  = (const float*)d_in[5];
    float*       out  = (float*)d_out;

    const int n4 = (N_NODES * OUT_FEATS) / 4;   // 1.6M float4

    // 1. zero accumulator + clear flag
    zero_kernel<<<(n4 + 255) / 256, 256>>>((float4*)out, n4);

    // 1b. detect index dtype (int32 vs int64)
    detect_kernel<<<1024, 256>>>((const unsigned int*)src);

    // 1c. normalize indices to int32
    convert_kernel<<<(N_EDGES + 255) / 256, 256>>>(src, dst);

    // 2. dense projection into g_h
    gemm_kernel<<<(N_NODES + MT - 1) / MT, 256>>>(feat, W_w, W_b);

    // 3. edge gather/scale/scatter-add (16 threads per edge)
    {
        long long total_threads = (long long)N_EDGES * 16LL;
        int blocks = (int)((total_threads + 255) / 256);   // 100000 blocks
        edge_kernel<<<blocks, 256>>>(e, out);
    }

    // 4. relu in place
    relu_kernel<<<(n4 + 255) / 256, 256>>>((float4*)out, n4);
}